// round 1
// baseline (speedup 1.0000x reference)
#include <cuda_runtime.h>
#include <cstdint>

// ---------------- constants (problem-fixed) ----------------
#define NNODES 100000
#define NEDGES 300000
#define DIN    128
#define HDIM   256
#define H2     512
#define NLAYER 4
#define NGRAPH 512
#define BN_EPS 1e-5f

// ---------------- scratch (device globals; no allocation allowed) ----------------
__device__ float g_h[NNODES * HDIM];      // current node features
__device__ float g_agg[NNODES * HDIM];    // (1+eps)h + scatter
__device__ float g_z1[NNODES * H2];       // MLP hidden
__device__ float g_z2[NNODES * HDIM];     // MLP out (pre-BN)
__device__ float g_stats[2 * HDIM];       // [sums | sumsq]
__device__ float g_pool[NGRAPH * HDIM];   // per-graph sums
__device__ float g_cnt[NGRAPH];           // per-graph counts

// ---------------- SGEMM: C = act(A[MxK] * B[KxN] + bias[N]) ----------------
// BM=128, BN=128, BK=8, 256 threads, 8x8 per thread. Requires K%8==0, N%128==0.
template <bool RELU>
__global__ __launch_bounds__(256, 2)
void sgemm_bias(const float* __restrict__ A, const float* __restrict__ B,
                const float* __restrict__ bias, float* __restrict__ C,
                int M, int N, int K)
{
    __shared__ float As[8][128];   // [k][m] transposed
    __shared__ float Bs[8][128];   // [k][n]

    const int tid = threadIdx.x;
    const int bm = blockIdx.y * 128;
    const int bn = blockIdx.x * 128;

    // A load mapping: float4 per thread along K
    const int arow = tid >> 1;           // 0..127
    const int acol = (tid & 1) << 2;     // 0 or 4
    // B load mapping: float4 per thread along N
    const int brow = tid >> 5;           // 0..7
    const int bcol = (tid & 31) << 2;    // 0..124

    const int tx = tid & 15;             // col group
    const int ty = tid >> 4;             // row group

    float acc[8][8];
#pragma unroll
    for (int i = 0; i < 8; i++)
#pragma unroll
        for (int j = 0; j < 8; j++) acc[i][j] = 0.0f;

    for (int k0 = 0; k0 < K; k0 += 8) {
        float4 av = make_float4(0.f, 0.f, 0.f, 0.f);
        if (bm + arow < M)
            av = *reinterpret_cast<const float4*>(&A[(size_t)(bm + arow) * K + k0 + acol]);
        As[acol + 0][arow] = av.x;
        As[acol + 1][arow] = av.y;
        As[acol + 2][arow] = av.z;
        As[acol + 3][arow] = av.w;

        float4 bv = *reinterpret_cast<const float4*>(&B[(size_t)(k0 + brow) * N + bn + bcol]);
        *reinterpret_cast<float4*>(&Bs[brow][bcol]) = bv;
        __syncthreads();

#pragma unroll
        for (int k = 0; k < 8; k++) {
            float ra[8], rb[8];
#pragma unroll
            for (int i = 0; i < 8; i += 4)
                *reinterpret_cast<float4*>(&ra[i]) =
                    *reinterpret_cast<const float4*>(&As[k][ty * 8 + i]);
#pragma unroll
            for (int j = 0; j < 8; j += 4)
                *reinterpret_cast<float4*>(&rb[j]) =
                    *reinterpret_cast<const float4*>(&Bs[k][tx * 8 + j]);
#pragma unroll
            for (int i = 0; i < 8; i++)
#pragma unroll
                for (int j = 0; j < 8; j++)
                    acc[i][j] = fmaf(ra[i], rb[j], acc[i][j]);
        }
        __syncthreads();
    }

    // epilogue: bias + optional relu
#pragma unroll
    for (int i = 0; i < 8; i++) {
        int row = bm + ty * 8 + i;
        if (row >= M) continue;
#pragma unroll
        for (int j = 0; j < 8; j += 4) {
            int col = bn + tx * 8 + j;
            float4 bvec = *reinterpret_cast<const float4*>(&bias[col]);
            float4 v;
            v.x = acc[i][j + 0] + bvec.x;
            v.y = acc[i][j + 1] + bvec.y;
            v.z = acc[i][j + 2] + bvec.z;
            v.w = acc[i][j + 3] + bvec.w;
            if (RELU) {
                v.x = fmaxf(v.x, 0.f); v.y = fmaxf(v.y, 0.f);
                v.z = fmaxf(v.z, 0.f); v.w = fmaxf(v.w, 0.f);
            }
            *reinterpret_cast<float4*>(&C[(size_t)row * N + col]) = v;
        }
    }
}

// ---------------- agg init: agg = (1+eps[layer]) * h ----------------
__global__ void init_agg_kernel(const float* __restrict__ h, const float* __restrict__ eps,
                                int layer, float* __restrict__ agg, int total4)
{
    int idx = blockIdx.x * blockDim.x + threadIdx.x;
    if (idx >= total4) return;
    float e = 1.0f + __ldg(&eps[layer]);
    float4 v = reinterpret_cast<const float4*>(h)[idx];
    v.x *= e; v.y *= e; v.z *= e; v.w *= e;
    reinterpret_cast<float4*>(agg)[idx] = v;
}

// ---------------- edge scatter: agg[dst] += h[src]  (64 threads per edge) ----------------
__global__ void scatter_kernel(const float* __restrict__ h, const int* __restrict__ src,
                               const int* __restrict__ dst, float* __restrict__ agg, int E)
{
    int idx = blockIdx.x * blockDim.x + threadIdx.x;
    int e = idx >> 6;
    if (e >= E) return;
    int c4 = (idx & 63) << 2;
    int s = __ldg(&src[e]);
    int d = __ldg(&dst[e]);
    float4 v = __ldg(reinterpret_cast<const float4*>(&h[(size_t)s * HDIM + c4]));
    float* o = &agg[(size_t)d * HDIM + c4];
    atomicAdd(o + 0, v.x);
    atomicAdd(o + 1, v.y);
    atomicAdd(o + 2, v.z);
    atomicAdd(o + 3, v.w);
}

// ---------------- BN statistics: per-channel sum & sumsq ----------------
__global__ void bn_stats_kernel(const float* __restrict__ z, float* __restrict__ stats, int n)
{
    int c = threadIdx.x;  // 256 threads == HDIM channels
    float s = 0.f, q = 0.f;
    for (int r = blockIdx.x; r < n; r += gridDim.x) {
        float v = z[(size_t)r * HDIM + c];
        s += v;
        q = fmaf(v, v, q);
    }
    atomicAdd(&stats[c], s);
    atomicAdd(&stats[HDIM + c], q);
}

// ---------------- BN apply + relu -> h ----------------
__global__ void bn_apply_kernel(const float* __restrict__ z, const float* __restrict__ stats,
                                const float* __restrict__ gamma, const float* __restrict__ beta,
                                float* __restrict__ hout, int total)
{
    int idx = blockIdx.x * blockDim.x + threadIdx.x;
    if (idx >= total) return;
    int c = idx & (HDIM - 1);
    const float invN = 1.0f / (float)NNODES;
    float mu = __ldg(&stats[c]) * invN;
    float var = __ldg(&stats[HDIM + c]) * invN - mu * mu;
    float sc = __ldg(&gamma[c]) * rsqrtf(var + BN_EPS);
    float v = (z[idx] - mu) * sc + __ldg(&beta[c]);
    hout[idx] = fmaxf(v, 0.f);
}

// ---------------- pooling: per-graph sums + counts ----------------
__global__ void pool_kernel(const float* __restrict__ h, const int* __restrict__ batch,
                            float* __restrict__ pooled, float* __restrict__ cnt, int n)
{
    int idx = blockIdx.x * blockDim.x + threadIdx.x;
    int node = idx >> 6;
    if (node >= n) return;
    int c4 = (idx & 63) << 2;
    int g = __ldg(&batch[node]);
    float4 v = __ldg(reinterpret_cast<const float4*>(&h[(size_t)node * HDIM + c4]));
    float* o = &pooled[(size_t)g * HDIM + c4];
    atomicAdd(o + 0, v.x);
    atomicAdd(o + 1, v.y);
    atomicAdd(o + 2, v.z);
    atomicAdd(o + 3, v.w);
    if (c4 == 0) atomicAdd(&cnt[g], 1.0f);
}

// ---------------- head: out[g] = relu(pooled_mean @ Wp1 + bp1) @ Wp2 + bp2 ----------------
__global__ void head_kernel(const float* __restrict__ pooled, const float* __restrict__ cnt,
                            const float* __restrict__ Wp1, const float* __restrict__ bp1,
                            const float* __restrict__ Wp2, const float* __restrict__ bp2,
                            float* __restrict__ out)
{
    __shared__ float sp[HDIM];
    __shared__ float red[128];
    int g = blockIdx.x;
    int tid = threadIdx.x;   // 128 threads
    float inv = 1.0f / fmaxf(__ldg(&cnt[g]), 1.0f);
    for (int k = tid; k < HDIM; k += 128)
        sp[k] = pooled[(size_t)g * HDIM + k] * inv;
    __syncthreads();

    float s = __ldg(&bp1[tid]);
#pragma unroll 4
    for (int k = 0; k < HDIM; k++)
        s = fmaf(sp[k], __ldg(&Wp1[k * 128 + tid]), s);
    s = fmaxf(s, 0.f);
    float t = s * __ldg(&Wp2[tid]);

    red[tid] = t;
    __syncthreads();
    for (int off = 64; off > 0; off >>= 1) {
        if (tid < off) red[tid] += red[tid + off];
        __syncthreads();
    }
    if (tid == 0) out[g] = red[0] + __ldg(&bp2[0]);
}

// ---------------- host launch ----------------
static float* sym_addr_f(const void* symbol)
{
    void* p = nullptr;
    cudaGetSymbolAddress(&p, symbol);
    return (float*)p;
}

extern "C" void kernel_launch(void* const* d_in, const int* in_sizes, int n_in,
                              void* d_out, int out_size)
{
    const float* x      = (const float*)d_in[0];
    const int*   ei     = (const int*)d_in[1];
    const int*   batch  = (const int*)d_in[2];
    const float* W_in   = (const float*)d_in[3];
    const float* b_in   = (const float*)d_in[4];
    const float* eps    = (const float*)d_in[5];
    const float* W1     = (const float*)d_in[6];
    const float* b1     = (const float*)d_in[7];
    const float* W2     = (const float*)d_in[8];
    const float* b2     = (const float*)d_in[9];
    const float* gamma  = (const float*)d_in[10];
    const float* beta   = (const float*)d_in[11];
    const float* Wp1    = (const float*)d_in[12];
    const float* bp1    = (const float*)d_in[13];
    const float* Wp2    = (const float*)d_in[14];
    const float* bp2    = (const float*)d_in[15];
    float* out = (float*)d_out;

    const int E = in_sizes[1] / 2;
    const int* src = ei;
    const int* dst = ei + E;

    float* h    = sym_addr_f(g_h);
    float* agg  = sym_addr_f(g_agg);
    float* z1   = sym_addr_f(g_z1);
    float* z2   = sym_addr_f(g_z2);
    float* stats = sym_addr_f(g_stats);
    float* pool = sym_addr_f(g_pool);
    float* cnt  = sym_addr_f(g_cnt);

    const int M = NNODES;
    dim3 blk(256);

    // 1) input projection: h = relu(x @ W_in + b_in)   [N,128]x[128,256]
    {
        dim3 grid(HDIM / 128, (M + 127) / 128);
        sgemm_bias<true><<<grid, blk>>>(x, W_in, b_in, h, M, HDIM, DIN);
    }

    const int totalH = M * HDIM;          // 25.6M
    const int total4 = totalH / 4;

    for (int l = 0; l < NLAYER; l++) {
        // 2) agg = (1+eps_l)*h
        init_agg_kernel<<<(total4 + 255) / 256, 256>>>(h, eps, l, agg, total4);
        // 3) agg[dst] += h[src]
        {
            long long tot = (long long)E * 64;
            scatter_kernel<<<(int)((tot + 255) / 256), 256>>>(h, src, dst, agg, E);
        }
        // 4) z1 = relu(agg @ W1_l + b1_l)  [N,256]x[256,512]
        {
            dim3 grid(H2 / 128, (M + 127) / 128);
            sgemm_bias<true><<<grid, blk>>>(agg, W1 + (size_t)l * HDIM * H2,
                                            b1 + (size_t)l * H2, z1, M, H2, HDIM);
        }
        // 5) z2 = z1 @ W2_l + b2_l        [N,512]x[512,256]
        {
            dim3 grid(HDIM / 128, (M + 127) / 128);
            sgemm_bias<false><<<grid, blk>>>(z1, W2 + (size_t)l * H2 * HDIM,
                                             b2 + (size_t)l * HDIM, z2, M, HDIM, H2);
        }
        // 6) BN stats
        cudaMemsetAsync(stats, 0, 2 * HDIM * sizeof(float));
        bn_stats_kernel<<<592, HDIM>>>(z2, stats, M);
        // 7) BN apply + relu -> h
        bn_apply_kernel<<<(totalH + 255) / 256, 256>>>(z2, stats,
                                                       gamma + (size_t)l * HDIM,
                                                       beta + (size_t)l * HDIM, h, totalH);
    }

    // 8) global mean pool
    cudaMemsetAsync(pool, 0, NGRAPH * HDIM * sizeof(float));
    cudaMemsetAsync(cnt, 0, NGRAPH * sizeof(float));
    {
        long long tot = (long long)M * 64;
        pool_kernel<<<(int)((tot + 255) / 256), 256>>>(h, batch, pool, cnt, M);
    }

    // 9) head
    head_kernel<<<NGRAPH, 128>>>(pool, cnt, Wp1, bp1, Wp2, bp2, out);
}

// round 3
// speedup vs baseline: 1.8430x; 1.8430x over previous
#include <cuda_runtime.h>
#include <cuda_bf16.h>
#include <cstdint>

// ---------------- constants (problem-fixed) ----------------
#define NNODES 100000
#define DIN    128
#define HDIM   256
#define H2     512
#define NLAYER 4
#define NGRAPH 512
#define BN_EPS 1e-5f

// ---------------- scratch (device globals; no allocation allowed) ----------------
__device__ float g_h[NNODES * HDIM];      // current node features
__device__ float g_agg[NNODES * HDIM];    // (1+eps)h + scatter
__device__ float g_z1[NNODES * H2];       // MLP hidden
__device__ float g_z2[NNODES * HDIM];     // MLP out (pre-BN)
__device__ float g_stats[2 * HDIM];       // [sums | sumsq]
__device__ float g_pool[NGRAPH * HDIM];   // per-graph sums
__device__ float g_cnt[NGRAPH];           // per-graph counts

// converted weights: transposed [N][K], bf16 hi/lo split
#define WIN_OFF  0
#define W1_OFF   (256 * 128)
#define W2_OFF   (W1_OFF + NLAYER * 512 * 256)
#define WT_TOTAL (W2_OFF + NLAYER * 256 * 512)
__device__ __align__(16) __nv_bfloat16 g_wh[WT_TOTAL];
__device__ __align__(16) __nv_bfloat16 g_wl[WT_TOTAL];

// ---------------- helpers ----------------
__device__ __forceinline__ uint32_t smem_u32(const void* p) {
    uint32_t a;
    asm("{ .reg .u64 t; cvta.to.shared.u64 t, %1; cvt.u32.u64 %0, t; }" : "=r"(a) : "l"(p));
    return a;
}
__device__ __forceinline__ uint32_t pkb(__nv_bfloat16 a, __nv_bfloat16 b) {
    __nv_bfloat162 t; t.x = a; t.y = b;
    return *reinterpret_cast<uint32_t*>(&t);
}
__device__ __forceinline__ void ldm4(uint32_t* r, uint32_t addr) {
    asm volatile("ldmatrix.sync.aligned.m8n8.x4.shared.b16 {%0,%1,%2,%3}, [%4];"
                 : "=r"(r[0]), "=r"(r[1]), "=r"(r[2]), "=r"(r[3]) : "r"(addr));
}
__device__ __forceinline__ void mma16816(float* c, const uint32_t* a, const uint32_t* b) {
    asm volatile("mma.sync.aligned.m16n8k16.row.col.f32.bf16.bf16.f32 "
                 "{%0,%1,%2,%3}, {%4,%5,%6,%7}, {%8,%9}, {%0,%1,%2,%3};"
                 : "+f"(c[0]), "+f"(c[1]), "+f"(c[2]), "+f"(c[3])
                 : "r"(a[0]), "r"(a[1]), "r"(a[2]), "r"(a[3]), "r"(b[0]), "r"(b[1]));
}

// smem stage layout: Ah(10240) Al(10240) Bh(10240) Bl(10240), 80B rows
#define ROWB  80
#define T_AH  0
#define T_AL  10240
#define T_BH  20480
#define T_BL  30720
#define STAGE 40960
#define SMEMB (2 * STAGE)

// ---------------- tensor-core GEMM via mma.sync bf16 hi/lo split ----------------
// C[M,N] = act(A[M,K]fp32 @ W[K,N] + bias); W pre-split to Bth/Btl [N][K] bf16.
// Block tile 128x128, K-chunk 32, 256 threads (warp tile 32x64), double-buffered.
// EPI: 0 = bias; 1 = bias+relu; 2 = bias+relu -> C, and C2 = (1+eps)*C.
template <int EPI>
__global__ __launch_bounds__(256, 1)
void tc_gemm(const float* __restrict__ A,
             const __nv_bfloat16* __restrict__ Bth, const __nv_bfloat16* __restrict__ Btl,
             const float* __restrict__ bias, float* __restrict__ C, float* __restrict__ C2,
             const float* __restrict__ epsp, int M, int N, int K)
{
    extern __shared__ __align__(16) char smraw[];
    const uint32_t sb = smem_u32(smraw);

    const int tid = threadIdx.x;
    const int lane = tid & 31, wid = tid >> 5;
    const int wm = (wid & 3) * 32;       // warp M offset (4 warps)
    const int wn = (wid >> 2) * 64;      // warp N offset (2 warps)
    const int bm = blockIdx.y * 128, bn = blockIdx.x * 128;
    const int nc = K / 32;

    float acc[2][8][4];
#pragma unroll
    for (int i = 0; i < 2; i++)
#pragma unroll
        for (int j = 0; j < 8; j++)
#pragma unroll
            for (int q = 0; q < 4; q++) acc[i][j][q] = 0.f;

    // A gmem mapping: 2 threads per row, 16 floats each
    const int arow = tid >> 1;
    const int acol = (tid & 1) * 16;
    int rg = bm + arow; if (rg >= M) rg = M - 1;
    const float* aptr = A + (size_t)rg * K + acol;
    const uint32_t aoff = (uint32_t)arow * ROWB + (uint32_t)acol * 2;

    float4 ar[4];

    // ---- prologue: chunk 0 ----
#pragma unroll
    for (int j = 0; j < 4; j++) ar[j] = __ldg((const float4*)(aptr + 4 * j));
#pragma unroll
    for (int i = 0; i < 4; i++) {
        int cc = tid + 256 * i;
        int v = cc >> 9, w = cc & 511, row = w >> 2, seg = w & 3;
        const __nv_bfloat16* src = (v ? Btl : Bth) + (size_t)(bn + row) * K + seg * 8;
        uint32_t dst = sb + (v ? T_BL : T_BH) + (uint32_t)row * ROWB + seg * 16;
        asm volatile("cp.async.ca.shared.global [%0], [%1], 16;" :: "r"(dst), "l"(src));
    }
    asm volatile("cp.async.commit_group;");
    {
        uint32_t dh = sb + T_AH + aoff, dl = sb + T_AL + aoff;
#pragma unroll
        for (int j = 0; j < 4; j++) {
            float4 v = ar[j];
            __nv_bfloat16 hx = __float2bfloat16(v.x), hy = __float2bfloat16(v.y);
            __nv_bfloat16 hz = __float2bfloat16(v.z), hw = __float2bfloat16(v.w);
            uint32_t h0 = pkb(hx, hy), h1 = pkb(hz, hw);
            uint32_t l0 = pkb(__float2bfloat16(v.x - __bfloat162float(hx)),
                              __float2bfloat16(v.y - __bfloat162float(hy)));
            uint32_t l1 = pkb(__float2bfloat16(v.z - __bfloat162float(hz)),
                              __float2bfloat16(v.w - __bfloat162float(hw)));
            asm volatile("st.shared.v2.b32 [%0], {%1,%2};" :: "r"(dh + j * 8), "r"(h0), "r"(h1) : "memory");
            asm volatile("st.shared.v2.b32 [%0], {%1,%2};" :: "r"(dl + j * 8), "r"(l0), "r"(l1) : "memory");
        }
    }
    asm volatile("cp.async.wait_group 0;");
    __syncthreads();

    // fragment address components
    const uint32_t a_ro = (uint32_t)(lane & 15) * ROWB + (uint32_t)(lane >> 4) * 16;
    const int brow = (lane & 7) + ((lane >> 4) << 3);
    const uint32_t b_ko = (uint32_t)((lane >> 3) & 1) * 16;

    for (int c = 0; c < nc; c++) {
        const uint32_t st0 = sb + (uint32_t)(c & 1) * STAGE;
        const uint32_t stn = sb + (uint32_t)((c + 1) & 1) * STAGE;
        const bool more = (c + 1 < nc);

        if (more) {
#pragma unroll
            for (int j = 0; j < 4; j++) ar[j] = __ldg((const float4*)(aptr + (c + 1) * 32 + 4 * j));
#pragma unroll
            for (int i = 0; i < 4; i++) {
                int cc = tid + 256 * i;
                int v = cc >> 9, w = cc & 511, row = w >> 2, seg = w & 3;
                const __nv_bfloat16* src = (v ? Btl : Bth) + (size_t)(bn + row) * K + (c + 1) * 32 + seg * 8;
                uint32_t dst = stn + (v ? T_BL : T_BH) + (uint32_t)row * ROWB + seg * 16;
                asm volatile("cp.async.ca.shared.global [%0], [%1], 16;" :: "r"(dst), "l"(src));
            }
            asm volatile("cp.async.commit_group;");
        }

        // ---- compute chunk c ----
#pragma unroll
        for (int ks = 0; ks < 2; ks++) {
            uint32_t ah[2][4], al[2][4], bh[4][4], bl[4][4];
            uint32_t abase = st0 + ks * 32 + a_ro + (uint32_t)wm * ROWB;
            ldm4(ah[0], abase + T_AH);
            ldm4(ah[1], abase + T_AH + 16 * ROWB);
            ldm4(al[0], abase + T_AL);
            ldm4(al[1], abase + T_AL + 16 * ROWB);
#pragma unroll
            for (int g = 0; g < 4; g++) {
                uint32_t bbase = st0 + ks * 32 + b_ko + (uint32_t)(wn + g * 16 + brow) * ROWB;
                ldm4(bh[g], bbase + T_BH);
                ldm4(bl[g], bbase + T_BL);
            }
            // sweep 1: Ah x Bh
#pragma unroll
            for (int mt = 0; mt < 2; mt++)
#pragma unroll
                for (int g = 0; g < 4; g++) {
                    mma16816(acc[mt][2 * g],     ah[mt], &bh[g][0]);
                    mma16816(acc[mt][2 * g + 1], ah[mt], &bh[g][2]);
                }
            // sweep 2: Al x Bh
#pragma unroll
            for (int mt = 0; mt < 2; mt++)
#pragma unroll
                for (int g = 0; g < 4; g++) {
                    mma16816(acc[mt][2 * g],     al[mt], &bh[g][0]);
                    mma16816(acc[mt][2 * g + 1], al[mt], &bh[g][2]);
                }
            // sweep 3: Ah x Bl
#pragma unroll
            for (int mt = 0; mt < 2; mt++)
#pragma unroll
                for (int g = 0; g < 4; g++) {
                    mma16816(acc[mt][2 * g],     ah[mt], &bl[g][0]);
                    mma16816(acc[mt][2 * g + 1], ah[mt], &bl[g][2]);
                }
        }

        if (more) {
            uint32_t dh = stn + T_AH + aoff, dl = stn + T_AL + aoff;
#pragma unroll
            for (int j = 0; j < 4; j++) {
                float4 v = ar[j];
                __nv_bfloat16 hx = __float2bfloat16(v.x), hy = __float2bfloat16(v.y);
                __nv_bfloat16 hz = __float2bfloat16(v.z), hw = __float2bfloat16(v.w);
                uint32_t h0 = pkb(hx, hy), h1 = pkb(hz, hw);
                uint32_t l0 = pkb(__float2bfloat16(v.x - __bfloat162float(hx)),
                                  __float2bfloat16(v.y - __bfloat162float(hy)));
                uint32_t l1 = pkb(__float2bfloat16(v.z - __bfloat162float(hz)),
                                  __float2bfloat16(v.w - __bfloat162float(hw)));
                asm volatile("st.shared.v2.b32 [%0], {%1,%2};" :: "r"(dh + j * 8), "r"(h0), "r"(h1) : "memory");
                asm volatile("st.shared.v2.b32 [%0], {%1,%2};" :: "r"(dl + j * 8), "r"(l0), "r"(l1) : "memory");
            }
        }
        asm volatile("cp.async.wait_group 0;");
        __syncthreads();
    }

    // ---- epilogue ----
    float emul = 0.f;
    if (EPI == 2) emul = 1.0f + __ldg(epsp);
#pragma unroll
    for (int mt = 0; mt < 2; mt++) {
        int r0 = bm + wm + mt * 16 + (lane >> 2);
        int r1 = r0 + 8;
#pragma unroll
        for (int nt = 0; nt < 8; nt++) {
            int col = bn + wn + nt * 8 + (lane & 3) * 2;
            float2 bv = *reinterpret_cast<const float2*>(&bias[col]);
            float v0 = acc[mt][nt][0] + bv.x;
            float v1 = acc[mt][nt][1] + bv.y;
            float v2 = acc[mt][nt][2] + bv.x;
            float v3 = acc[mt][nt][3] + bv.y;
            if (EPI >= 1) {
                v0 = fmaxf(v0, 0.f); v1 = fmaxf(v1, 0.f);
                v2 = fmaxf(v2, 0.f); v3 = fmaxf(v3, 0.f);
            }
            if (r0 < M) {
                *reinterpret_cast<float2*>(&C[(size_t)r0 * N + col]) = make_float2(v0, v1);
                if (EPI == 2)
                    *reinterpret_cast<float2*>(&C2[(size_t)r0 * N + col]) = make_float2(emul * v0, emul * v1);
            }
            if (r1 < M) {
                *reinterpret_cast<float2*>(&C[(size_t)r1 * N + col]) = make_float2(v2, v3);
                if (EPI == 2)
                    *reinterpret_cast<float2*>(&C2[(size_t)r1 * N + col]) = make_float2(emul * v2, emul * v3);
            }
        }
    }
}

// ---------------- weight transpose + bf16 split: dst[n][k] = split(src[k][n]) ----------------
__global__ void conv_w(const float* __restrict__ src, __nv_bfloat16* __restrict__ dh,
                       __nv_bfloat16* __restrict__ dl, int K, int N)
{
    int idx = blockIdx.x * blockDim.x + threadIdx.x;
    if (idx >= K * N) return;
    int n = idx / K, k = idx % K;
    float v = src[(size_t)k * N + n];
    __nv_bfloat16 h = __float2bfloat16(v);
    __nv_bfloat16 l = __float2bfloat16(v - __bfloat162float(h));
    dh[idx] = h; dl[idx] = l;
}

// ---------------- edge scatter: agg[dst] += h[src] ----------------
__global__ void scatter_kernel(const float* __restrict__ h, const int* __restrict__ src,
                               const int* __restrict__ dst, float* __restrict__ agg, int E)
{
    int idx = blockIdx.x * blockDim.x + threadIdx.x;
    int e = idx >> 6;
    if (e >= E) return;
    int c4 = (idx & 63) << 2;
    int s = __ldg(&src[e]);
    int d = __ldg(&dst[e]);
    float4 v = __ldg(reinterpret_cast<const float4*>(&h[(size_t)s * HDIM + c4]));
    float* o = &agg[(size_t)d * HDIM + c4];
    atomicAdd(o + 0, v.x);
    atomicAdd(o + 1, v.y);
    atomicAdd(o + 2, v.z);
    atomicAdd(o + 3, v.w);
}

// ---------------- BN statistics ----------------
__global__ void bn_stats_kernel(const float* __restrict__ z, float* __restrict__ stats, int n)
{
    int c = threadIdx.x;  // 256 threads == HDIM channels
    float s = 0.f, q = 0.f;
    for (int r = blockIdx.x; r < n; r += gridDim.x) {
        float v = z[(size_t)r * HDIM + c];
        s += v;
        q = fmaf(v, v, q);
    }
    atomicAdd(&stats[c], s);
    atomicAdd(&stats[HDIM + c], q);
}

// ---------------- BN apply + relu -> h (and agg = (1+eps_next)*h) ----------------
__global__ void bn_apply_kernel(const float4* __restrict__ z, const float* __restrict__ stats,
                                const float* __restrict__ gamma, const float* __restrict__ beta,
                                const float* __restrict__ epsn,
                                float4* __restrict__ h, float4* __restrict__ agg, int total4)
{
    int i = blockIdx.x * blockDim.x + threadIdx.x;
    if (i >= total4) return;
    int c = (i << 2) & (HDIM - 1);
    const float invN = 1.0f / (float)NNODES;
    float4 s = *reinterpret_cast<const float4*>(&stats[c]);
    float4 q = *reinterpret_cast<const float4*>(&stats[HDIM + c]);
    float4 g = *reinterpret_cast<const float4*>(&gamma[c]);
    float4 b = *reinterpret_cast<const float4*>(&beta[c]);
    float4 zv = z[i];
    float4 r;
    {
        float mu = s.x * invN, var = q.x * invN - mu * mu;
        r.x = fmaxf((zv.x - mu) * (g.x * rsqrtf(var + BN_EPS)) + b.x, 0.f);
    }
    {
        float mu = s.y * invN, var = q.y * invN - mu * mu;
        r.y = fmaxf((zv.y - mu) * (g.y * rsqrtf(var + BN_EPS)) + b.y, 0.f);
    }
    {
        float mu = s.z * invN, var = q.z * invN - mu * mu;
        r.z = fmaxf((zv.z - mu) * (g.z * rsqrtf(var + BN_EPS)) + b.z, 0.f);
    }
    {
        float mu = s.w * invN, var = q.w * invN - mu * mu;
        r.w = fmaxf((zv.w - mu) * (g.w * rsqrtf(var + BN_EPS)) + b.w, 0.f);
    }
    h[i] = r;
    if (agg) {
        float e = 1.0f + __ldg(epsn);
        float4 a; a.x = e * r.x; a.y = e * r.y; a.z = e * r.z; a.w = e * r.w;
        agg[i] = a;
    }
}

// ---------------- pooling ----------------
__global__ void pool_kernel(const float* __restrict__ h, const int* __restrict__ batch,
                            float* __restrict__ pooled, float* __restrict__ cnt, int n)
{
    int idx = blockIdx.x * blockDim.x + threadIdx.x;
    int node = idx >> 6;
    if (node >= n) return;
    int c4 = (idx & 63) << 2;
    int g = __ldg(&batch[node]);
    float4 v = __ldg(reinterpret_cast<const float4*>(&h[(size_t)node * HDIM + c4]));
    float* o = &pooled[(size_t)g * HDIM + c4];
    atomicAdd(o + 0, v.x);
    atomicAdd(o + 1, v.y);
    atomicAdd(o + 2, v.z);
    atomicAdd(o + 3, v.w);
    if (c4 == 0) atomicAdd(&cnt[g], 1.0f);
}

// ---------------- predictor head ----------------
__global__ void head_kernel(const float* __restrict__ pooled, const float* __restrict__ cnt,
                            const float* __restrict__ Wp1, const float* __restrict__ bp1,
                            const float* __restrict__ Wp2, const float* __restrict__ bp2,
                            float* __restrict__ out)
{
    __shared__ float sp[HDIM];
    __shared__ float red[128];
    int g = blockIdx.x;
    int tid = threadIdx.x;   // 128 threads
    float inv = 1.0f / fmaxf(__ldg(&cnt[g]), 1.0f);
    for (int k = tid; k < HDIM; k += 128)
        sp[k] = pooled[(size_t)g * HDIM + k] * inv;
    __syncthreads();

    float s = __ldg(&bp1[tid]);
#pragma unroll 4
    for (int k = 0; k < HDIM; k++)
        s = fmaf(sp[k], __ldg(&Wp1[k * 128 + tid]), s);
    s = fmaxf(s, 0.f);
    float t = s * __ldg(&Wp2[tid]);

    red[tid] = t;
    __syncthreads();
    for (int off = 64; off > 0; off >>= 1) {
        if (tid < off) red[tid] += red[tid + off];
        __syncthreads();
    }
    if (tid == 0) out[g] = red[0] + __ldg(&bp2[0]);
}

// ---------------- host launch ----------------
static void* sym_addr(const void* symbol)
{
    void* p = nullptr;
    cudaGetSymbolAddress(&p, symbol);
    return p;
}

extern "C" void kernel_launch(void* const* d_in, const int* in_sizes, int n_in,
                              void* d_out, int out_size)
{
    const float* x      = (const float*)d_in[0];
    const int*   ei     = (const int*)d_in[1];
    const int*   batch  = (const int*)d_in[2];
    const float* W_in   = (const float*)d_in[3];
    const float* b_in   = (const float*)d_in[4];
    const float* eps    = (const float*)d_in[5];
    const float* W1     = (const float*)d_in[6];
    const float* b1     = (const float*)d_in[7];
    const float* W2     = (const float*)d_in[8];
    const float* b2     = (const float*)d_in[9];
    const float* gamma  = (const float*)d_in[10];
    const float* beta   = (const float*)d_in[11];
    const float* Wp1    = (const float*)d_in[12];
    const float* bp1    = (const float*)d_in[13];
    const float* Wp2    = (const float*)d_in[14];
    const float* bp2    = (const float*)d_in[15];
    float* out = (float*)d_out;

    const int E = in_sizes[1] / 2;
    const int* src = ei;
    const int* dst = ei + E;

    float* h     = (float*)sym_addr(g_h);
    float* agg   = (float*)sym_addr(g_agg);
    float* z1    = (float*)sym_addr(g_z1);
    float* z2    = (float*)sym_addr(g_z2);
    float* stats = (float*)sym_addr(g_stats);
    float* pool  = (float*)sym_addr(g_pool);
    float* cnt   = (float*)sym_addr(g_cnt);
    __nv_bfloat16* wh = (__nv_bfloat16*)sym_addr(g_wh);
    __nv_bfloat16* wl = (__nv_bfloat16*)sym_addr(g_wl);

    cudaFuncSetAttribute(tc_gemm<0>, cudaFuncAttributeMaxDynamicSharedMemorySize, SMEMB);
    cudaFuncSetAttribute(tc_gemm<1>, cudaFuncAttributeMaxDynamicSharedMemorySize, SMEMB);
    cudaFuncSetAttribute(tc_gemm<2>, cudaFuncAttributeMaxDynamicSharedMemorySize, SMEMB);

    const int M = NNODES;
    const int mt = (M + 127) / 128;    // 782
    const int totalH = M * HDIM;
    const int total4 = totalH / 4;

    // ---- weight prep: transpose + bf16 hi/lo split ----
    conv_w<<<(DIN * HDIM + 255) / 256, 256>>>(W_in, wh + WIN_OFF, wl + WIN_OFF, DIN, HDIM);
    for (int l = 0; l < NLAYER; l++) {
        conv_w<<<(HDIM * H2 + 255) / 256, 256>>>(W1 + (size_t)l * HDIM * H2,
                                                 wh + W1_OFF + (size_t)l * H2 * HDIM,
                                                 wl + W1_OFF + (size_t)l * H2 * HDIM, HDIM, H2);
        conv_w<<<(H2 * HDIM + 255) / 256, 256>>>(W2 + (size_t)l * H2 * HDIM,
                                                 wh + W2_OFF + (size_t)l * HDIM * H2,
                                                 wl + W2_OFF + (size_t)l * HDIM * H2, H2, HDIM);
    }

    // ---- input projection: h = relu(x@W_in + b_in), agg = (1+eps0)*h ----
    tc_gemm<2><<<dim3(2, mt), 256, SMEMB>>>(x, wh + WIN_OFF, wl + WIN_OFF, b_in,
                                            h, agg, eps, M, HDIM, DIN);

    for (int l = 0; l < NLAYER; l++) {
        // agg[dst] += h[src]
        {
            long long tot = (long long)E * 64;
            scatter_kernel<<<(int)((tot + 255) / 256), 256>>>(h, src, dst, agg, E);
        }
        // z1 = relu(agg @ W1_l + b1_l)
        tc_gemm<1><<<dim3(4, mt), 256, SMEMB>>>(agg, wh + W1_OFF + (size_t)l * H2 * HDIM,
                                                wl + W1_OFF + (size_t)l * H2 * HDIM,
                                                b1 + (size_t)l * H2, z1, nullptr, nullptr,
                                                M, H2, HDIM);
        // z2 = z1 @ W2_l + b2_l
        tc_gemm<0><<<dim3(2, mt), 256, SMEMB>>>(z1, wh + W2_OFF + (size_t)l * HDIM * H2,
                                                wl + W2_OFF + (size_t)l * HDIM * H2,
                                                b2 + (size_t)l * HDIM, z2, nullptr, nullptr,
                                                M, HDIM, H2);
        // BN stats
        cudaMemsetAsync(stats, 0, 2 * HDIM * sizeof(float));
        bn_stats_kernel<<<592, HDIM>>>(z2, stats, M);
        // BN apply + relu -> h (and agg for next layer)
        const float* epsn = eps + ((l + 1 < NLAYER) ? (l + 1) : l);
        bn_apply_kernel<<<(total4 + 255) / 256, 256>>>((const float4*)z2, stats,
                                                       gamma + (size_t)l * HDIM,
                                                       beta + (size_t)l * HDIM, epsn,
                                                       (float4*)h,
                                                       (l + 1 < NLAYER) ? (float4*)agg : nullptr,
                                                       total4);
    }

    // ---- global mean pool ----
    cudaMemsetAsync(pool, 0, NGRAPH * HDIM * sizeof(float));
    cudaMemsetAsync(cnt, 0, NGRAPH * sizeof(float));
    {
        long long tot = (long long)M * 64;
        pool_kernel<<<(int)((tot + 255) / 256), 256>>>(h, batch, pool, cnt, M);
    }

    // ---- head ----
    head_kernel<<<NGRAPH, 128>>>(pool, cnt, Wp1, bp1, Wp2, bp2, out);
}